// round 1
// baseline (speedup 1.0000x reference)
#include <cuda_runtime.h>
#include <cuda_bf16.h>

// ---------------- problem constants ----------------
#define D_MODEL 1024
#define D_STATE 16
#define D_CONV  4
#define D_INNER 2048
#define DT_RANK 64
#define BSZ 2
#define SEQ 1024
#define MROWS (BSZ * SEQ)          // 2048
#define DBL_W (DT_RANK + 2 * D_STATE)  // 96

// ---------------- scratch (static device memory; allocation-free) ----------
__device__ float g_xflip[MROWS * D_MODEL];
__device__ float g_xz   [2][MROWS * 2 * D_INNER];
__device__ float g_xc   [2][MROWS * D_INNER];
__device__ float g_dbl  [2][MROWS * DBL_W];
__device__ float g_delta[2][MROWS * D_INNER];
__device__ float g_y    [2][MROWS * D_INNER];
__device__ float g_fb   [MROWS * 2 * D_MODEL];

// ---------------- helpers ----------------
__device__ __forceinline__ float sigmoidf_(float x) {
    return 1.0f / (1.0f + __expf(-x));
}
__device__ __forceinline__ float softplusf_(float x) {
    // matches jax.nn.softplus to ~1e-7 rel in the relevant range
    return (x > 20.0f) ? x : log1pf(expf(x));
}

// ---------------- flip kernel: x -> g_xflip (reverse L within batch) -------
__global__ void flip_kernel(const float* __restrict__ x, float* __restrict__ o) {
    int idx = blockIdx.x * blockDim.x + threadIdx.x;
    if (idx >= MROWS * D_MODEL) return;
    int row = idx / D_MODEL;
    int d   = idx % D_MODEL;
    int src = (row ^ (SEQ - 1));       // flip low 10 bits = reverse l within b
    o[idx] = x[src * D_MODEL + d];
}

// ---------------- conv1d (depthwise causal, k=4) + SiLU --------------------
__global__ void conv_silu_kernel(const float* __restrict__ xz,
                                 const float* __restrict__ cw,
                                 const float* __restrict__ cb,
                                 float* __restrict__ xc) {
    int idx = blockIdx.x * blockDim.x + threadIdx.x;
    if (idx >= MROWS * D_INNER) return;
    int row = idx / D_INNER;
    int e   = idx % D_INNER;
    int l   = row % SEQ;
    int b0  = row - l;                 // b*SEQ
    float acc = cb[e];
    #pragma unroll
    for (int k = 0; k < D_CONV; k++) {
        int ll = l - (D_CONV - 1) + k;
        if (ll >= 0)
            acc = fmaf(cw[e * D_CONV + k], xz[(b0 + ll) * (2 * D_INNER) + e], acc);
    }
    xc[idx] = acc * sigmoidf_(acc);    // SiLU
}

// ---------------- generic NT GEMM: C[m,n] = sum_k A[m,k]*W[n,k] ------------
// EPI: 0 = plain, 1 = softplus(acc + bias[n])
// FLIP: output row m -> m ^ 1023 (sequence reversal for bwd direction)
template <int EPI, bool FLIP>
__global__ void gemm_nt(const float* __restrict__ A, const float* __restrict__ W,
                        float* __restrict__ C, const float* __restrict__ bias,
                        int M, int N, int K, int lda, int ldb, int ldc) {
    const int BK = 16;
    __shared__ float As[BK][68];
    __shared__ float Bs[BK][68];

    int tid = threadIdx.x;             // 256 threads
    int m0 = blockIdx.y * 64;
    int n0 = blockIdx.x * 64;
    int tx = tid & 15;
    int ty = tid >> 4;
    int lrow = tid >> 2;               // 0..63
    int lk   = (tid & 3) * 4;          // 0,4,8,12

    float acc[4][4];
    #pragma unroll
    for (int i = 0; i < 4; i++)
        #pragma unroll
        for (int j = 0; j < 4; j++) acc[i][j] = 0.0f;

    for (int k0 = 0; k0 < K; k0 += BK) {
        float4 av = *(const float4*)(A + (size_t)(m0 + lrow) * lda + k0 + lk);
        float4 wv = make_float4(0.f, 0.f, 0.f, 0.f);
        if (n0 + lrow < N)
            wv = *(const float4*)(W + (size_t)(n0 + lrow) * ldb + k0 + lk);
        As[lk + 0][lrow] = av.x; As[lk + 1][lrow] = av.y;
        As[lk + 2][lrow] = av.z; As[lk + 3][lrow] = av.w;
        Bs[lk + 0][lrow] = wv.x; Bs[lk + 1][lrow] = wv.y;
        Bs[lk + 2][lrow] = wv.z; Bs[lk + 3][lrow] = wv.w;
        __syncthreads();

        #pragma unroll
        for (int kk = 0; kk < BK; kk++) {
            float4 a = *(const float4*)&As[kk][ty * 4];
            float4 b = *(const float4*)&Bs[kk][tx * 4];
            acc[0][0] = fmaf(a.x, b.x, acc[0][0]);
            acc[0][1] = fmaf(a.x, b.y, acc[0][1]);
            acc[0][2] = fmaf(a.x, b.z, acc[0][2]);
            acc[0][3] = fmaf(a.x, b.w, acc[0][3]);
            acc[1][0] = fmaf(a.y, b.x, acc[1][0]);
            acc[1][1] = fmaf(a.y, b.y, acc[1][1]);
            acc[1][2] = fmaf(a.y, b.z, acc[1][2]);
            acc[1][3] = fmaf(a.y, b.w, acc[1][3]);
            acc[2][0] = fmaf(a.z, b.x, acc[2][0]);
            acc[2][1] = fmaf(a.z, b.y, acc[2][1]);
            acc[2][2] = fmaf(a.z, b.z, acc[2][2]);
            acc[2][3] = fmaf(a.z, b.w, acc[2][3]);
            acc[3][0] = fmaf(a.w, b.x, acc[3][0]);
            acc[3][1] = fmaf(a.w, b.y, acc[3][1]);
            acc[3][2] = fmaf(a.w, b.z, acc[3][2]);
            acc[3][3] = fmaf(a.w, b.w, acc[3][3]);
        }
        __syncthreads();
    }

    #pragma unroll
    for (int i = 0; i < 4; i++) {
        int m = m0 + ty * 4 + i;
        int mo = FLIP ? (m ^ (SEQ - 1)) : m;
        #pragma unroll
        for (int j = 0; j < 4; j++) {
            int n = n0 + tx * 4 + j;
            if (n < N) {
                float v = acc[i][j];
                if (EPI == 1) v = softplusf_(v + bias[n]);
                C[(size_t)mo * ldc + n] = v;
            }
        }
    }
}

// ---------------- selective scan ----------------
// one thread per (b, e, n). 16-lane group reduce for y. Fused D-skip + gate.
__global__ void scan_kernel(const float* __restrict__ delta,
                            const float* __restrict__ xc,
                            const float* __restrict__ dbl,
                            const float* __restrict__ xz,   // z = cols [D_INNER, 2*D_INNER)
                            const float* __restrict__ A_log,
                            const float* __restrict__ Dp,
                            float* __restrict__ y) {
    int tid = threadIdx.x;                      // 256
    int g = tid >> 4;                           // 0..15 channel-in-block
    int n = tid & 15;                           // state index
    int e = blockIdx.x * 16 + g;
    int b = blockIdx.y;
    int base = b * SEQ;

    float A = -expf(A_log[e * D_STATE + n]);
    float De = Dp[e];
    float h = 0.0f;

    for (int l = 0; l < SEQ; l++) {
        int row = base + l;
        float dv = delta[(size_t)row * D_INNER + e];
        float xv = xc   [(size_t)row * D_INNER + e];
        float Bn = dbl  [(size_t)row * DBL_W + DT_RANK + n];
        float Cn = dbl  [(size_t)row * DBL_W + DT_RANK + D_STATE + n];

        float dA = __expf(dv * A);
        h = fmaf(dA, h, dv * xv * Bn);
        float p = h * Cn;
        // sum over the 16 state lanes
        #pragma unroll
        for (int o = 1; o < 16; o <<= 1)
            p += __shfl_xor_sync(0xffffffffu, p, o);

        if (n == 0) {
            float zv = xz[(size_t)row * (2 * D_INNER) + D_INNER + e];
            float yv = (p + xv * De) * (zv * sigmoidf_(zv));
            y[(size_t)row * D_INNER + e] = yv;
        }
    }
}

// ---------------- host launcher ----------------
extern "C" void kernel_launch(void* const* d_in, const int* in_sizes, int n_in,
                              void* d_out, int out_size) {
    const float* x = (const float*)d_in[0];
    // per-direction params: [1+9*dir + k]
    //   0:in_proj 1:conv_w 2:conv_b 3:x_proj 4:dt_w 5:dt_b 6:A_log 7:D 8:out_proj
    const float* merge_w = (const float*)d_in[19];
    float* out = (float*)d_out;

    float *xflip, *xz, *xc, *dbl, *delta, *y, *fb;
    cudaGetSymbolAddress((void**)&xflip, g_xflip);
    cudaGetSymbolAddress((void**)&xz,    g_xz);
    cudaGetSymbolAddress((void**)&xc,    g_xc);
    cudaGetSymbolAddress((void**)&dbl,   g_dbl);
    cudaGetSymbolAddress((void**)&delta, g_delta);
    cudaGetSymbolAddress((void**)&y,     g_y);
    cudaGetSymbolAddress((void**)&fb,    g_fb);

    const size_t XZ_SZ  = (size_t)MROWS * 2 * D_INNER;
    const size_t XC_SZ  = (size_t)MROWS * D_INNER;
    const size_t DBL_SZ = (size_t)MROWS * DBL_W;

    // 1) flipped copy of x for the bwd direction
    flip_kernel<<<(MROWS * D_MODEL + 255) / 256, 256>>>(x, xflip);

    for (int dir = 0; dir < 2; dir++) {
        const float* in_proj = (const float*)d_in[1 + 9 * dir + 0];
        const float* conv_w  = (const float*)d_in[1 + 9 * dir + 1];
        const float* conv_b  = (const float*)d_in[1 + 9 * dir + 2];
        const float* x_proj  = (const float*)d_in[1 + 9 * dir + 3];
        const float* dt_w    = (const float*)d_in[1 + 9 * dir + 4];
        const float* dt_b    = (const float*)d_in[1 + 9 * dir + 5];
        const float* A_log   = (const float*)d_in[1 + 9 * dir + 6];
        const float* Dp      = (const float*)d_in[1 + 9 * dir + 7];

        const float* Ain = dir ? xflip : x;
        float* xz_d    = xz    + dir * XZ_SZ;
        float* xc_d    = xc    + dir * XC_SZ;
        float* dbl_d   = dbl   + dir * DBL_SZ;
        float* delta_d = delta + dir * XC_SZ;
        float* y_d     = y     + dir * XC_SZ;

        // in_proj: (2048 x 1024) @ (4096 x 1024)^T -> (2048 x 4096)
        gemm_nt<0, false><<<dim3(2 * D_INNER / 64, MROWS / 64), 256>>>(
            Ain, in_proj, xz_d, nullptr,
            MROWS, 2 * D_INNER, D_MODEL, D_MODEL, D_MODEL, 2 * D_INNER);

        // depthwise causal conv + SiLU
        conv_silu_kernel<<<(MROWS * D_INNER + 255) / 256, 256>>>(
            xz_d, conv_w, conv_b, xc_d);

        // x_proj: (2048 x 2048) @ (96 x 2048)^T -> (2048 x 96)
        gemm_nt<0, false><<<dim3((DBL_W + 63) / 64, MROWS / 64), 256>>>(
            xc_d, x_proj, dbl_d, nullptr,
            MROWS, DBL_W, D_INNER, D_INNER, D_INNER, DBL_W);

        // delta = softplus(dt @ dt_w^T + dt_b): (2048 x 64)@(2048 x 64)^T
        gemm_nt<1, false><<<dim3(D_INNER / 64, MROWS / 64), 256>>>(
            dbl_d, dt_w, delta_d, dt_b,
            MROWS, D_INNER, DT_RANK, DBL_W, DT_RANK, D_INNER);

        // selective scan (+ D skip + SiLU(z) gate)
        scan_kernel<<<dim3(D_INNER / 16, BSZ), 256>>>(
            delta_d, xc_d, dbl_d, xz_d, A_log, Dp, y_d);
    }

    // out_proj fwd -> fb[:, 0:1024]
    gemm_nt<0, false><<<dim3(D_MODEL / 64, MROWS / 64), 256>>>(
        y, (const float*)d_in[1 + 8], fb, nullptr,
        MROWS, D_MODEL, D_INNER, D_INNER, D_INNER, 2 * D_MODEL);
    // out_proj bwd -> fb[:, 1024:2048], rows flipped back to forward order
    gemm_nt<0, true><<<dim3(D_MODEL / 64, MROWS / 64), 256>>>(
        y + XC_SZ, (const float*)d_in[1 + 9 + 8], fb + D_MODEL, nullptr,
        MROWS, D_MODEL, D_INNER, D_INNER, D_INNER, 2 * D_MODEL);

    // merge: (2048 x 2048) @ (1024 x 2048)^T -> (2048 x 1024)
    gemm_nt<0, false><<<dim3(D_MODEL / 64, MROWS / 64), 256>>>(
        fb, merge_w, out, nullptr,
        MROWS, D_MODEL, 2 * D_MODEL, 2 * D_MODEL, 2 * D_MODEL, D_MODEL);
}